// round 1
// baseline (speedup 1.0000x reference)
#include <cuda_runtime.h>

#define Nn   100000
#define Ee   1600000
#define Bb   2
#define FIN  116
#define EMBD 12
#define Hh   128
#define KP   120      // FIN padded to multiple of 8
#define NSTAGE (KP/8) // 15
#define NC   128      // accumulator copies for contention spreading

// -------- scratch (static device globals; no allocation) --------
__device__ float g_xw1[(size_t)Nn * Bb * Hh];  // [n][b][h] interleaved, 102.4 MB
__device__ int   g_cnt[Nn];
__device__ int   g_cursor[Nn];
__device__ float g_dis[Nn];
__device__ float g_tsum[Nn];
__device__ int   g_rowstart[Nn + 1];
__device__ int   g_csrc[Ee];
__device__ float g_cw[Ee];
__device__ float g_T[8 * Hh];          // embed @ W1[116:128,:]
__device__ float g_acc[NC * 256];      // spread accumulator copies [copy][b*128+f]

// -------- kernels --------
__global__ void k_zero() {
    int i = blockIdx.x * blockDim.x + threadIdx.x;
    int stride = gridDim.x * blockDim.x;
    for (int j = i; j < Nn; j += stride) { g_cnt[j] = 0; g_cursor[j] = 0; g_tsum[j] = 0.f; }
    for (int j = i; j < NC * 256; j += stride) g_acc[j] = 0.f;
}

__global__ void k_hist(const int* __restrict__ dst) {
    int i = blockIdx.x * blockDim.x + threadIdx.x;
    int stride = gridDim.x * blockDim.x;
    for (int e = i; e < Ee; e += stride) atomicAdd(&g_cnt[dst[e]], 1);
}

__global__ void k_dis() {
    int i = blockIdx.x * blockDim.x + threadIdx.x;
    if (i < Nn) g_dis[i] = rsqrtf((float)g_cnt[i] + 1.0f);
}

__global__ void k_tsum(const int* __restrict__ src, const int* __restrict__ dst) {
    int i = blockIdx.x * blockDim.x + threadIdx.x;
    int stride = gridDim.x * blockDim.x;
    for (int e = i; e < Ee; e += stride) atomicAdd(&g_tsum[src[e]], g_dis[dst[e]]);
}

// exclusive prefix sum of g_cnt -> g_rowstart (single block, 1024 threads)
__global__ void k_scan() {
    __shared__ int sd[1024];
    __shared__ int carry;
    int t = threadIdx.x;
    if (t == 0) carry = 0;
    __syncthreads();
    for (int base = 0; base < Nn; base += 1024) {
        int idx = base + t;
        int v = (idx < Nn) ? g_cnt[idx] : 0;
        sd[t] = v;
        __syncthreads();
        for (int off = 1; off < 1024; off <<= 1) {
            int x = (t >= off) ? sd[t - off] : 0;
            __syncthreads();
            sd[t] += x;
            __syncthreads();
        }
        if (idx < Nn) g_rowstart[idx] = carry + sd[t] - v;  // exclusive
        int tot = sd[1023];
        __syncthreads();
        if (t == 0) carry += tot;
        __syncthreads();
    }
    if (t == 0) g_rowstart[Nn] = carry;
}

__global__ void k_scatter(const int* __restrict__ src, const int* __restrict__ dst) {
    int i = blockIdx.x * blockDim.x + threadIdx.x;
    int stride = gridDim.x * blockDim.x;
    for (int e = i; e < Ee; e += stride) {
        int d = dst[e], s = src[e];
        int pos = g_rowstart[d] + atomicAdd(&g_cursor[d], 1);
        g_csrc[pos] = s;
        g_cw[pos] = g_dis[s];
    }
}

// T[e][h] = sum_j embed[e][j] * W1[(116+j)][h]
__global__ void k_embtab(const float* __restrict__ embed, const float* __restrict__ W1) {
    int idx = blockIdx.x * blockDim.x + threadIdx.x;
    if (idx < 8 * Hh) {
        int e = idx >> 7, h = idx & 127;
        float s = 0.f;
        #pragma unroll
        for (int j = 0; j < EMBD; j++) s += embed[e * EMBD + j] * W1[(FIN + j) * Hh + h];
        g_T[idx] = s;
    }
}

// xw1[n][b][h] = node[b][n][:116] @ W1[:116,:] + T[ntype[n]][h]
// 128x128 tiles, 256 threads, 8x8 micro-tiles, double-buffered smem staging.
__global__ __launch_bounds__(256, 2) void k_gemm(const float* __restrict__ node,
                                                 const int* __restrict__ ntype,
                                                 const float* __restrict__ W1) {
    __shared__ float As[2][8][128];
    __shared__ float Ws[2][8][128];
    int b = blockIdx.y;
    int n0 = blockIdx.x * 128;
    int t = threadIdx.x;
    int r0 = (t >> 4) << 3;
    int c0 = (t & 15) << 3;
    const float* Abase = node + (size_t)b * Nn * FIN;

    float acc[8][8];
    #pragma unroll
    for (int i = 0; i < 8; i++)
        #pragma unroll
        for (int j = 0; j < 8; j++) acc[i][j] = 0.f;

    // prologue: stage 0
    {
        int k0 = 0;
        #pragma unroll
        for (int i = 0; i < 4; i++) {
            int lin = i * 256 + t;
            int row = lin >> 3, kk = lin & 7;
            int n = n0 + row, k = k0 + kk;
            As[0][kk][row] = (n < Nn && k < FIN) ? Abase[(size_t)n * FIN + k] : 0.f;
        }
        #pragma unroll
        for (int i = 0; i < 4; i++) {
            int lin = i * 256 + t;
            int kk = lin >> 7, h = lin & 127;
            int k = k0 + kk;
            Ws[0][kk][h] = (k < FIN) ? W1[k * Hh + h] : 0.f;
        }
    }
    __syncthreads();

    for (int s = 0; s < NSTAGE; s++) {
        int cur = s & 1, nxt = cur ^ 1;
        float rA[4], rW[4];
        if (s + 1 < NSTAGE) {
            int k0 = (s + 1) * 8;
            #pragma unroll
            for (int i = 0; i < 4; i++) {
                int lin = i * 256 + t;
                int row = lin >> 3, kk = lin & 7;
                int n = n0 + row, k = k0 + kk;
                rA[i] = (n < Nn && k < FIN) ? Abase[(size_t)n * FIN + k] : 0.f;
            }
            #pragma unroll
            for (int i = 0; i < 4; i++) {
                int lin = i * 256 + t;
                int kk = lin >> 7, h = lin & 127;
                int k = k0 + kk;
                rW[i] = (k < FIN) ? W1[k * Hh + h] : 0.f;
            }
        }
        #pragma unroll
        for (int kk = 0; kk < 8; kk++) {
            float a[8], w[8];
            #pragma unroll
            for (int x = 0; x < 8; x++) a[x] = As[cur][kk][r0 + x];
            #pragma unroll
            for (int x = 0; x < 8; x++) w[x] = Ws[cur][kk][c0 + x];
            #pragma unroll
            for (int rr = 0; rr < 8; rr++)
                #pragma unroll
                for (int cc = 0; cc < 8; cc++) acc[rr][cc] += a[rr] * w[cc];
        }
        if (s + 1 < NSTAGE) {
            #pragma unroll
            for (int i = 0; i < 4; i++) {
                int lin = i * 256 + t;
                int row = lin >> 3, kk = lin & 7;
                As[nxt][kk][row] = rA[i];
            }
            #pragma unroll
            for (int i = 0; i < 4; i++) {
                int lin = i * 256 + t;
                int kk = lin >> 7, h = lin & 127;
                Ws[nxt][kk][h] = rW[i];
            }
        }
        __syncthreads();
    }

    #pragma unroll
    for (int rr = 0; rr < 8; rr++) {
        int n = n0 + r0 + rr;
        if (n < Nn) {
            int e = ntype[n];
            float* o = g_xw1 + ((size_t)n * Bb + b) * Hh + c0;
            const float* Tb = g_T + e * Hh + c0;
            #pragma unroll
            for (int cc = 0; cc < 8; cc++) o[cc] = acc[rr][cc] + Tb[cc];
        }
    }
}

// one block per dst node; 256 threads = (b = t>>7, f = t&127)
// computes h = relu(Ahat*xw1 + b1) for node i and accumulates s[i]*h into g_acc copies
__global__ __launch_bounds__(256) void k_agg(const float* __restrict__ b1) {
    int i = blockIdx.x;
    int t = threadIdx.x;
    __shared__ int   ss[128];
    __shared__ float sw[128];
    int beg = g_rowstart[i], end = g_rowstart[i + 1];
    float d = g_dis[i];
    float acc = 0.f;
    for (int c0 = beg; c0 < end; c0 += 128) {
        int m = end - c0;
        if (m > 128) m = 128;
        __syncthreads();
        if (t < m) { ss[t] = g_csrc[c0 + t] * 256; sw[t] = g_cw[c0 + t]; }
        __syncthreads();
        int e = 0;
        for (; e + 4 <= m; e += 4) {
            float x0 = __ldg(g_xw1 + ss[e + 0] + t);
            float x1 = __ldg(g_xw1 + ss[e + 1] + t);
            float x2 = __ldg(g_xw1 + ss[e + 2] + t);
            float x3 = __ldg(g_xw1 + ss[e + 3] + t);
            acc += sw[e + 0] * x0;
            acc += sw[e + 1] * x1;
            acc += sw[e + 2] * x2;
            acc += sw[e + 3] * x3;
        }
        for (; e < m; e++) acc += sw[e] * __ldg(g_xw1 + ss[e] + t);
    }
    float self = g_xw1[i * 256 + t];
    float total = d * acc + d * d * self;
    float h = fmaxf(total + b1[t & 127], 0.f);
    float sI = d * (g_tsum[i] + d);
    atomicAdd(&g_acc[(i & (NC - 1)) * 256 + t], sI * h);
}

// out[b][h2] = b2[h2] + (1/N) * sum_f v[b][f] * W2[f][h2]
__global__ void k_final(const float* __restrict__ W2, const float* __restrict__ b2,
                        float* __restrict__ out) {
    __shared__ float v[256];
    int t = threadIdx.x;
    float s = 0.f;
    for (int c = 0; c < NC; c++) s += g_acc[c * 256 + t];
    v[t] = s * (1.0f / (float)Nn);
    __syncthreads();
    int b = t >> 7, h2 = t & 127;
    float o = b2[h2];
    for (int f = 0; f < 128; f++) o += v[b * 128 + f] * W2[f * Hh + h2];
    out[b * Hh + h2] = o;
}

extern "C" void kernel_launch(void* const* d_in, const int* in_sizes, int n_in,
                              void* d_out, int out_size) {
    const float* node  = (const float*)d_in[0];
    const int*   ntype = (const int*)d_in[1];
    const int*   ei    = (const int*)d_in[2];
    const float* embed = (const float*)d_in[3];
    const float* W1    = (const float*)d_in[4];
    const float* b1    = (const float*)d_in[5];
    const float* W2    = (const float*)d_in[6];
    const float* b2    = (const float*)d_in[7];
    const int* src = ei;
    const int* dst = ei + Ee;

    k_zero<<<256, 256>>>();
    k_hist<<<1024, 256>>>(dst);
    k_dis<<<(Nn + 255) / 256, 256>>>();
    k_tsum<<<1024, 256>>>(src, dst);
    k_scan<<<1, 1024>>>();
    k_scatter<<<1024, 256>>>(src, dst);
    k_embtab<<<4, 256>>>(embed, W1);
    k_gemm<<<dim3((Nn + 127) / 128, Bb), 256>>>(node, ntype, W1);
    k_agg<<<Nn, 256>>>(b1);
    k_final<<<1, 256>>>(W2, b2, (float*)d_out);
}

// round 5
// speedup vs baseline: 1.6219x; 1.6219x over previous
#include <cuda_runtime.h>
#include <cuda_fp16.h>
#include <cstdint>

#define Nn   100000
#define Ee   1600000
#define Bb   2
#define FIN  116
#define EMBD 12
#define Hh   128
#define KP   120
#define NS   15          // K chunks of 8
#define NC   128         // accumulator copies
#define NPB  16          // nodes per agg block

// -------- scratch (static device globals) --------
__device__ __half g_xw1h[(size_t)Nn * 256];   // [n][h][b] packed half2: 51.2 MB (L2-resident)
__device__ int   g_cnt[Nn];
__device__ int   g_cursor[Nn];
__device__ float g_dis[Nn];
__device__ float g_tsum[Nn];
__device__ int   g_rowstart[Nn + 1];
__device__ int   g_csrc[Ee];
__device__ float g_cw[Ee];
__device__ float g_T[8 * Hh];
__device__ float g_acc[NC * 256];
__device__ float g_W1hi[KP * Hh];
__device__ float g_W1lo[KP * Hh];

// -------- small helpers --------
__device__ __forceinline__ uint32_t f2tf32(float x) {
    uint32_t r; asm("cvt.rna.tf32.f32 %0, %1;" : "=r"(r) : "f"(x)); return r;
}
__device__ __forceinline__ void cp4(uint32_t dst, const void* src, bool pred) {
    int sz = pred ? 4 : 0;
    asm volatile("cp.async.ca.shared.global [%0], [%1], 4, %2;\n" :: "r"(dst), "l"(src), "r"(sz));
}
#define CP_COMMIT() asm volatile("cp.async.commit_group;\n" ::: "memory")
#define CP_WAIT1()  asm volatile("cp.async.wait_group 1;\n" ::: "memory")

#define MMA_TF32(Cr, Ar, B0, B1)                                              \
    asm volatile("mma.sync.aligned.m16n8k8.row.col.f32.tf32.tf32.f32 "        \
                 "{%0,%1,%2,%3},{%4,%5,%6,%7},{%8,%9},{%0,%1,%2,%3};"         \
                 : "+f"(Cr[0]), "+f"(Cr[1]), "+f"(Cr[2]), "+f"(Cr[3])         \
                 : "r"(Ar[0]), "r"(Ar[1]), "r"(Ar[2]), "r"(Ar[3]),            \
                   "r"(B0), "r"(B1))

// -------- prep kernels --------
__global__ void k_zero() {
    int i = blockIdx.x * blockDim.x + threadIdx.x;
    int stride = gridDim.x * blockDim.x;
    for (int j = i; j < Nn; j += stride) { g_cnt[j] = 0; g_cursor[j] = 0; g_tsum[j] = 0.f; }
    for (int j = i; j < NC * 256; j += stride) g_acc[j] = 0.f;
}

__global__ void k_hist(const int* __restrict__ dst) {
    int i = blockIdx.x * blockDim.x + threadIdx.x;
    int stride = gridDim.x * blockDim.x;
    for (int e = i; e < Ee; e += stride) atomicAdd(&g_cnt[dst[e]], 1);
}

__global__ void k_dis() {
    int i = blockIdx.x * blockDim.x + threadIdx.x;
    if (i < Nn) g_dis[i] = rsqrtf((float)g_cnt[i] + 1.0f);
}

__global__ void k_tsum(const int* __restrict__ src, const int* __restrict__ dst) {
    int i = blockIdx.x * blockDim.x + threadIdx.x;
    int stride = gridDim.x * blockDim.x;
    for (int e = i; e < Ee; e += stride) atomicAdd(&g_tsum[src[e]], g_dis[dst[e]]);
}

__global__ void k_scan() {
    __shared__ int sd[1024];
    __shared__ int carry;
    int t = threadIdx.x;
    if (t == 0) carry = 0;
    __syncthreads();
    for (int base = 0; base < Nn; base += 1024) {
        int idx = base + t;
        int v = (idx < Nn) ? g_cnt[idx] : 0;
        sd[t] = v;
        __syncthreads();
        for (int off = 1; off < 1024; off <<= 1) {
            int x = (t >= off) ? sd[t - off] : 0;
            __syncthreads();
            sd[t] += x;
            __syncthreads();
        }
        if (idx < Nn) g_rowstart[idx] = carry + sd[t] - v;
        int tot = sd[1023];
        __syncthreads();
        if (t == 0) carry += tot;
        __syncthreads();
    }
    if (t == 0) g_rowstart[Nn] = carry;
}

__global__ void k_scatter(const int* __restrict__ src, const int* __restrict__ dst) {
    int i = blockIdx.x * blockDim.x + threadIdx.x;
    int stride = gridDim.x * blockDim.x;
    for (int e = i; e < Ee; e += stride) {
        int d = dst[e], s = src[e];
        int pos = g_rowstart[d] + atomicAdd(&g_cursor[d], 1);
        g_csrc[pos] = s;
        g_cw[pos] = g_dis[s];
    }
}

__global__ void k_embtab(const float* __restrict__ embed, const float* __restrict__ W1) {
    int idx = blockIdx.x * blockDim.x + threadIdx.x;
    if (idx < 8 * Hh) {
        int e = idx >> 7, h = idx & 127;
        float s = 0.f;
        #pragma unroll
        for (int j = 0; j < EMBD; j++) s += embed[e * EMBD + j] * W1[(FIN + j) * Hh + h];
        g_T[idx] = s;
    }
}

// split W1[:116,:] into tf32 hi+lo, zero-pad rows 116..119
__global__ void k_wsplit(const float* __restrict__ W1) {
    int idx = blockIdx.x * blockDim.x + threadIdx.x;
    if (idx < KP * Hh) {
        int k = idx >> 7;
        float w = (k < FIN) ? W1[idx] : 0.f;
        float hi = __uint_as_float(f2tf32(w));
        g_W1hi[idx] = hi;
        g_W1lo[idx] = __uint_as_float(f2tf32(w - hi));
    }
}

// -------- tensor-core GEMM: xw1 = x @ W1 (tf32 split-B), epilogue adds embed table, stores half --------
__global__ __launch_bounds__(256, 2) void k_gemm(const float* __restrict__ node,
                                                 const int* __restrict__ ntype) {
    __shared__ float As[2][8][136];
    __shared__ float Bh[2][8][136];
    __shared__ float Bl[2][8][136];
    int b = blockIdx.y;
    int n0 = blockIdx.x * 128;
    int t = threadIdx.x;
    int w = t >> 5, lane = t & 31;
    int wm = w & 3, wn = w >> 2;         // warp tile: rows wm*32, cols wn*64
    int g = lane >> 2, t4 = lane & 3;
    const float* Abase = node + (size_t)b * Nn * FIN;

    uint32_t sAs = (uint32_t)__cvta_generic_to_shared(&As[0][0][0]);
    uint32_t sBh = (uint32_t)__cvta_generic_to_shared(&Bh[0][0][0]);
    uint32_t sBl = (uint32_t)__cvta_generic_to_shared(&Bl[0][0][0]);

    float C[2][8][4];
    #pragma unroll
    for (int mt = 0; mt < 2; mt++)
        #pragma unroll
        for (int nt = 0; nt < 8; nt++)
            #pragma unroll
            for (int x = 0; x < 4; x++) C[mt][nt][x] = 0.f;

    int arow = t >> 3, akk = t & 7;       // A loader: row = arow+32i, k = akk
    int bh_ = t & 127, bkk0 = t >> 7;     // B loader: k = 2i+bkk0, h

    auto issue = [&](int s) {
        int k0 = s * 8;
        int buf = s & 1;
        #pragma unroll
        for (int i = 0; i < 4; i++) {
            int row = arow + 32 * i;
            int n = n0 + row, k = k0 + akk;
            bool ok = (n < Nn) && (k < FIN);
            const float* src = ok ? (Abase + (size_t)n * FIN + k) : Abase;
            cp4(sAs + (((buf * 8 + akk) * 136 + row) << 2), src, ok);
        }
        #pragma unroll
        for (int i = 0; i < 4; i++) {
            int kk = 2 * i + bkk0;
            int k = k0 + kk;
            cp4(sBh + (((buf * 8 + kk) * 136 + bh_) << 2), g_W1hi + k * Hh + bh_, true);
            cp4(sBl + (((buf * 8 + kk) * 136 + bh_) << 2), g_W1lo + k * Hh + bh_, true);
        }
    };

    issue(0);
    CP_COMMIT();

    for (int s = 0; s < NS; s++) {
        if (s + 1 < NS) issue(s + 1);
        CP_COMMIT();
        CP_WAIT1();
        __syncthreads();
        int buf = s & 1;

        uint32_t a[2][4];
        #pragma unroll
        for (int mt = 0; mt < 2; mt++) {
            int R = wm * 32 + mt * 16;
            a[mt][0] = f2tf32(As[buf][t4][R + g]);
            a[mt][1] = f2tf32(As[buf][t4][R + g + 8]);
            a[mt][2] = f2tf32(As[buf][t4 + 4][R + g]);
            a[mt][3] = f2tf32(As[buf][t4 + 4][R + g + 8]);
        }
        #pragma unroll
        for (int nt = 0; nt < 8; nt++) {
            int h0 = wn * 64 + nt * 8;
            uint32_t bh0 = __float_as_uint(Bh[buf][t4][h0 + g]);
            uint32_t bh1 = __float_as_uint(Bh[buf][t4 + 4][h0 + g]);
            uint32_t bl0 = __float_as_uint(Bl[buf][t4][h0 + g]);
            uint32_t bl1 = __float_as_uint(Bl[buf][t4 + 4][h0 + g]);
            MMA_TF32(C[0][nt], a[0], bh0, bh1);
            MMA_TF32(C[1][nt], a[1], bh0, bh1);
            MMA_TF32(C[0][nt], a[0], bl0, bl1);
            MMA_TF32(C[1][nt], a[1], bl0, bl1);
        }
        __syncthreads();
    }

    // epilogue: add embed-table term, store half at [n][h][b]
    #pragma unroll
    for (int mt = 0; mt < 2; mt++) {
        int r0 = n0 + wm * 32 + mt * 16 + g;
        int r1 = r0 + 8;
        int e0 = (r0 < Nn) ? ntype[r0] : 0;
        int e1 = (r1 < Nn) ? ntype[r1] : 0;
        #pragma unroll
        for (int nt = 0; nt < 8; nt++) {
            int h = wn * 64 + nt * 8 + 2 * t4;
            if (r0 < Nn) {
                float v0 = C[mt][nt][0] + g_T[e0 * Hh + h];
                float v1 = C[mt][nt][1] + g_T[e0 * Hh + h + 1];
                g_xw1h[(size_t)r0 * 256 + h * 2 + b]       = __float2half(v0);
                g_xw1h[(size_t)r0 * 256 + (h + 1) * 2 + b] = __float2half(v1);
            }
            if (r1 < Nn) {
                float v2 = C[mt][nt][2] + g_T[e1 * Hh + h];
                float v3 = C[mt][nt][3] + g_T[e1 * Hh + h + 1];
                g_xw1h[(size_t)r1 * 256 + h * 2 + b]       = __float2half(v2);
                g_xw1h[(size_t)r1 * 256 + (h + 1) * 2 + b] = __float2half(v3);
            }
        }
    }
}

// -------- aggregation: 16 nodes per block, 128 threads (one feature, both batches via half2) --------
__global__ __launch_bounds__(128) void k_agg(const float* __restrict__ b1) {
    int i0 = blockIdx.x * NPB;
    int t = threadIdx.x;
    __shared__ int   ss[128];
    __shared__ float sw[128];
    const __half2* X = (const __half2*)g_xw1h;
    float bb = b1[t];
    float acc0 = 0.f, acc1 = 0.f;
    int iend = i0 + NPB; if (iend > Nn) iend = Nn;

    for (int i = i0; i < iend; i++) {
        int beg = g_rowstart[i], end = g_rowstart[i + 1];
        float d = g_dis[i];
        float a0 = 0.f, a1 = 0.f;
        for (int c0 = beg; c0 < end; c0 += 128) {
            int m = end - c0; if (m > 128) m = 128;
            __syncthreads();
            if (t < m) { ss[t] = g_csrc[c0 + t] * 128; sw[t] = g_cw[c0 + t]; }
            __syncthreads();
            int e = 0;
            for (; e + 4 <= m; e += 4) {
                float2 v0 = __half22float2(__ldg(X + ss[e + 0] + t));
                float2 v1 = __half22float2(__ldg(X + ss[e + 1] + t));
                float2 v2 = __half22float2(__ldg(X + ss[e + 2] + t));
                float2 v3 = __half22float2(__ldg(X + ss[e + 3] + t));
                a0 += sw[e + 0] * v0.x + sw[e + 1] * v1.x + sw[e + 2] * v2.x + sw[e + 3] * v3.x;
                a1 += sw[e + 0] * v0.y + sw[e + 1] * v1.y + sw[e + 2] * v2.y + sw[e + 3] * v3.y;
            }
            for (; e < m; e++) {
                float2 v = __half22float2(__ldg(X + ss[e] + t));
                a0 += sw[e] * v.x;
                a1 += sw[e] * v.y;
            }
        }
        float2 self = __half22float2(X[(size_t)i * 128 + t]);
        float h0 = fmaxf(d * a0 + d * d * self.x + bb, 0.f);
        float h1 = fmaxf(d * a1 + d * d * self.y + bb, 0.f);
        float sI = d * (g_tsum[i] + d);
        acc0 += sI * h0;
        acc1 += sI * h1;
    }
    int ci = (blockIdx.x & (NC - 1)) * 256;
    atomicAdd(&g_acc[ci + t], acc0);
    atomicAdd(&g_acc[ci + 128 + t], acc1);
}

// -------- final: out[b][h2] = b2 + (1/N) * v[b] @ W2 --------
__global__ void k_final(const float* __restrict__ W2, const float* __restrict__ b2,
                        float* __restrict__ out) {
    __shared__ float v[256];
    int t = threadIdx.x;
    float s = 0.f;
    for (int c = 0; c < NC; c++) s += g_acc[c * 256 + t];
    v[t] = s * (1.0f / (float)Nn);
    __syncthreads();
    int b = t >> 7, h2 = t & 127;
    float o = b2[h2];
    for (int f = 0; f < 128; f++) o += v[b * 128 + f] * W2[f * Hh + h2];
    out[b * Hh + h2] = o;
}

extern "C" void kernel_launch(void* const* d_in, const int* in_sizes, int n_in,
                              void* d_out, int out_size) {
    const float* node  = (const float*)d_in[0];
    const int*   ntype = (const int*)d_in[1];
    const int*   ei    = (const int*)d_in[2];
    const float* embed = (const float*)d_in[3];
    const float* W1    = (const float*)d_in[4];
    const float* b1    = (const float*)d_in[5];
    const float* W2    = (const float*)d_in[6];
    const float* b2    = (const float*)d_in[7];
    const int* src = ei;
    const int* dst = ei + Ee;

    k_zero<<<256, 256>>>();
    k_hist<<<1024, 256>>>(dst);
    k_dis<<<(Nn + 255) / 256, 256>>>();
    k_tsum<<<1024, 256>>>(src, dst);
    k_scan<<<1, 1024>>>();
    k_scatter<<<1024, 256>>>(src, dst);
    k_embtab<<<4, 256>>>(embed, W1);
    k_wsplit<<<(KP * Hh + 255) / 256, 256>>>(W1);
    k_gemm<<<dim3((Nn + 127) / 128, Bb), 256>>>(node, ntype);
    k_agg<<<(Nn + NPB - 1) / NPB, 128>>>(b1);
    k_final<<<1, 256>>>(W2, b2, (float*)d_out);
}

// round 9
// speedup vs baseline: 2.3548x; 1.4519x over previous
#include <cuda_runtime.h>
#include <cuda_fp16.h>
#include <cuda_bf16.h>
#include <cstdint>

#define Nn   100000
#define Ee   1600000
#define Bb   2
#define FIN  116
#define EMBD 12
#define Hh   128
#define NS2  8           // K chunks of 16 (K padded to 128)
#define NC   128         // accumulator copies
#define NPB  16          // nodes per agg block
#define NSB  98          // scan blocks (ceil(100000/1024))

// -------- scratch (static device globals) --------
__device__ __half g_xw1h[(size_t)Nn * 256];   // [n][h][b] packed half2: 51.2 MB
__device__ int   g_cnt[Nn];
__device__ int   g_cursor[Nn];
__device__ float g_dis[Nn];
__device__ float g_tsum[Nn];
__device__ int   g_rowstart[Nn + 1];
__device__ int   g_bsum[NSB];
__device__ int   g_csrc[Ee];
__device__ float g_cw[Ee];
__device__ float g_T[8 * Hh];
__device__ float g_acc[NC * 256];
__device__ uint32_t g_W1p[2][64][Hh];  // [split hi/lo][kpair][h] bf16x2 packed (k even=lo half)

// -------- small helpers --------
__device__ __forceinline__ uint32_t packbf(float lo, float hi) {
    uint32_t r; asm("cvt.rn.bf16x2.f32 %0, %1, %2;" : "=r"(r) : "f"(hi), "f"(lo)); return r;
}
__device__ __forceinline__ void cp4(uint32_t dst, const void* src, bool pred) {
    int sz = pred ? 4 : 0;
    asm volatile("cp.async.ca.shared.global [%0], [%1], 4, %2;\n" :: "r"(dst), "l"(src), "r"(sz));
}
#define CP_COMMIT() asm volatile("cp.async.commit_group;\n" ::: "memory")
#define CP_WAIT1()  asm volatile("cp.async.wait_group 1;\n" ::: "memory")

#define MMA_BF16(Cr, Ar, B0, B1)                                              \
    asm volatile("mma.sync.aligned.m16n8k16.row.col.f32.bf16.bf16.f32 "       \
                 "{%0,%1,%2,%3},{%4,%5,%6,%7},{%8,%9},{%0,%1,%2,%3};"         \
                 : "+f"(Cr[0]), "+f"(Cr[1]), "+f"(Cr[2]), "+f"(Cr[3])         \
                 : "r"(Ar[0]), "r"(Ar[1]), "r"(Ar[2]), "r"(Ar[3]),            \
                   "r"(B0), "r"(B1))

// -------- prep kernels --------
__global__ void k_zero() {
    int i = blockIdx.x * blockDim.x + threadIdx.x;
    int stride = gridDim.x * blockDim.x;
    for (int j = i; j < Nn; j += stride) { g_cnt[j] = 0; g_cursor[j] = 0; g_tsum[j] = 0.f; }
    for (int j = i; j < NC * 256; j += stride) g_acc[j] = 0.f;
}

__global__ void k_hist(const int* __restrict__ dst) {
    int i = blockIdx.x * blockDim.x + threadIdx.x;
    int stride = gridDim.x * blockDim.x;
    for (int e = i; e < Ee; e += stride) atomicAdd(&g_cnt[dst[e]], 1);
}

__global__ void k_dis() {
    int i = blockIdx.x * blockDim.x + threadIdx.x;
    if (i < Nn) g_dis[i] = rsqrtf((float)g_cnt[i] + 1.0f);
}

// ---- 3-phase parallel scan ----
__global__ void k_scanA() {
    __shared__ int sd[1024];
    int t = threadIdx.x;
    int idx = blockIdx.x * 1024 + t;
    int v = (idx < Nn) ? g_cnt[idx] : 0;
    sd[t] = v;
    __syncthreads();
    for (int off = 1; off < 1024; off <<= 1) {
        int x = (t >= off) ? sd[t - off] : 0;
        __syncthreads();
        sd[t] += x;
        __syncthreads();
    }
    if (idx < Nn) g_rowstart[idx] = sd[t] - v;   // block-local exclusive
    if (t == 1023) g_bsum[blockIdx.x] = sd[1023];
}

__global__ void k_scanB() {
    if (threadIdx.x == 0) {
        int c = 0;
        for (int i = 0; i < NSB; i++) { int v = g_bsum[i]; g_bsum[i] = c; c += v; }
        g_rowstart[Nn] = c;
    }
}

__global__ void k_scanC() {
    int t = threadIdx.x;
    int idx = blockIdx.x * 1024 + t;
    if (idx < Nn) g_rowstart[idx] += g_bsum[blockIdx.x];
}

// scatter + fused tsum
__global__ void k_scatter(const int* __restrict__ src, const int* __restrict__ dst) {
    int i = blockIdx.x * blockDim.x + threadIdx.x;
    int stride = gridDim.x * blockDim.x;
    for (int e = i; e < Ee; e += stride) {
        int d = dst[e], s = src[e];
        int pos = g_rowstart[d] + atomicAdd(&g_cursor[d], 1);
        g_csrc[pos] = s;
        g_cw[pos] = g_dis[s];
        atomicAdd(&g_tsum[s], g_dis[d]);
    }
}

__global__ void k_embtab(const float* __restrict__ embed, const float* __restrict__ W1) {
    int idx = blockIdx.x * blockDim.x + threadIdx.x;
    if (idx < 8 * Hh) {
        int e = idx >> 7, h = idx & 127;
        float s = 0.f;
        #pragma unroll
        for (int j = 0; j < EMBD; j++) s += embed[e * EMBD + j] * W1[(FIN + j) * Hh + h];
        g_T[idx] = s;
    }
}

// split W1[:116,:] into bf16 hi+lo, packed by k-pairs; zero-pad k>=116
__global__ void k_wsplit(const float* __restrict__ W1) {
    int idx = blockIdx.x * blockDim.x + threadIdx.x;
    if (idx < 64 * Hh) {
        int kp = idx >> 7, h = idx & 127;
        int k0 = 2 * kp, k1 = 2 * kp + 1;
        float w0 = (k0 < FIN) ? W1[k0 * Hh + h] : 0.f;
        float w1 = (k1 < FIN) ? W1[k1 * Hh + h] : 0.f;
        float h0 = __bfloat162float(__float2bfloat16(w0));
        float h1 = __bfloat162float(__float2bfloat16(w1));
        float l0 = w0 - h0, l1 = w1 - h1;
        g_W1p[0][kp][h] = packbf(h0, h1);
        g_W1p[1][kp][h] = packbf(l0, l1);
    }
}

// -------- bf16 tensor-core GEMM: xw1 = x @ W1 (split-B hi/lo), epilogue adds embed table, stores half --------
__global__ __launch_bounds__(256, 2) void k_gemm(const float* __restrict__ node,
                                                 const int* __restrict__ ntype) {
    __shared__ float    As[2][16][137];
    __shared__ uint32_t Bp[2][2][8][136];   // [buf][split][kpair][h]
    int b = blockIdx.y;
    int n0 = blockIdx.x * 128;
    int t = threadIdx.x;
    int w = t >> 5, lane = t & 31;
    int wm = w & 3, wn = w >> 2;         // warp tile: rows wm*32, cols wn*64
    int g = lane >> 2, t4 = lane & 3;
    const float* Abase = node + (size_t)b * Nn * FIN;

    uint32_t sAs = (uint32_t)__cvta_generic_to_shared(&As[0][0][0]);
    uint32_t sBp = (uint32_t)__cvta_generic_to_shared(&Bp[0][0][0][0]);

    float C[2][8][4];
    #pragma unroll
    for (int mt = 0; mt < 2; mt++)
        #pragma unroll
        for (int nt = 0; nt < 8; nt++)
            #pragma unroll
            for (int x = 0; x < 4; x++) C[mt][nt][x] = 0.f;

    auto issue = [&](int s) {
        int k0 = s * 16;
        int buf = s & 1;
        // A: 128 rows x 16 k = 2048 floats, 8 per thread
        #pragma unroll
        for (int i = 0; i < 8; i++) {
            int lin = i * 256 + t;
            int row = lin >> 4, kk = lin & 15;
            int n = n0 + row, k = k0 + kk;
            bool ok = (n < Nn) && (k < FIN);
            const float* srcp = ok ? (Abase + (size_t)n * FIN + k) : Abase;
            cp4(sAs + (((buf * 16 + kk) * 137 + row) << 2), srcp, ok);
        }
        // B: 2 splits x 8 kpairs x 128 h = 2048 words, 8 per thread
        #pragma unroll
        for (int i = 0; i < 8; i++) {
            int lin = i * 256 + t;
            int h = lin & 127;
            int kp = (lin >> 7) & 7;
            int sp = lin >> 10;
            cp4(sBp + ((((buf * 2 + sp) * 8 + kp) * 136 + h) << 2),
                &g_W1p[sp][s * 8 + kp][h], true);
        }
    };

    issue(0);
    CP_COMMIT();

    for (int s = 0; s < NS2; s++) {
        if (s + 1 < NS2) issue(s + 1);
        CP_COMMIT();
        CP_WAIT1();
        __syncthreads();
        int buf = s & 1;

        uint32_t a[2][4];
        #pragma unroll
        for (int mt = 0; mt < 2; mt++) {
            int R = wm * 32 + mt * 16;
            a[mt][0] = packbf(As[buf][2 * t4][R + g],     As[buf][2 * t4 + 1][R + g]);
            a[mt][1] = packbf(As[buf][2 * t4][R + g + 8], As[buf][2 * t4 + 1][R + g + 8]);
            a[mt][2] = packbf(As[buf][2 * t4 + 8][R + g],     As[buf][2 * t4 + 9][R + g]);
            a[mt][3] = packbf(As[buf][2 * t4 + 8][R + g + 8], As[buf][2 * t4 + 9][R + g + 8]);
        }
        #pragma unroll
        for (int nt = 0; nt < 8; nt++) {
            int c = wn * 64 + nt * 8 + g;
            uint32_t bh0 = Bp[buf][0][t4][c];
            uint32_t bh1 = Bp[buf][0][t4 + 4][c];
            uint32_t bl0 = Bp[buf][1][t4][c];
            uint32_t bl1 = Bp[buf][1][t4 + 4][c];
            MMA_BF16(C[0][nt], a[0], bh0, bh1);
            MMA_BF16(C[1][nt], a[1], bh0, bh1);
            MMA_BF16(C[0][nt], a[0], bl0, bl1);
            MMA_BF16(C[1][nt], a[1], bl0, bl1);
        }
        __syncthreads();
    }

    // epilogue: add embed-table term, store half at [n][h][b]
    #pragma unroll
    for (int mt = 0; mt < 2; mt++) {
        int r0 = n0 + wm * 32 + mt * 16 + g;
        int r1 = r0 + 8;
        int e0 = (r0 < Nn) ? ntype[r0] : 0;
        int e1 = (r1 < Nn) ? ntype[r1] : 0;
        #pragma unroll
        for (int nt = 0; nt < 8; nt++) {
            int h = wn * 64 + nt * 8 + 2 * t4;
            if (r0 < Nn) {
                float v0 = C[mt][nt][0] + g_T[e0 * Hh + h];
                float v1 = C[mt][nt][1] + g_T[e0 * Hh + h + 1];
                g_xw1h[(size_t)r0 * 256 + h * 2 + b]       = __float2half(v0);
                g_xw1h[(size_t)r0 * 256 + (h + 1) * 2 + b] = __float2half(v1);
            }
            if (r1 < Nn) {
                float v2 = C[mt][nt][2] + g_T[e1 * Hh + h];
                float v3 = C[mt][nt][3] + g_T[e1 * Hh + h + 1];
                g_xw1h[(size_t)r1 * 256 + h * 2 + b]       = __float2half(v2);
                g_xw1h[(size_t)r1 * 256 + (h + 1) * 2 + b] = __float2half(v3);
            }
        }
    }
}

// -------- aggregation: 16 nodes per block, 128 threads (one feature, both batches via half2) --------
__global__ __launch_bounds__(128) void k_agg(const float* __restrict__ b1) {
    int i0 = blockIdx.x * NPB;
    int t = threadIdx.x;
    __shared__ int   ss[128];
    __shared__ float sw[128];
    const __half2* X = (const __half2*)g_xw1h;
    float bb = b1[t];
    float acc0 = 0.f, acc1 = 0.f;
    int iend = i0 + NPB; if (iend > Nn) iend = Nn;

    for (int i = i0; i < iend; i++) {
        int beg = g_rowstart[i], end = g_rowstart[i + 1];
        float d = g_dis[i];
        float a0 = 0.f, a1 = 0.f;
        for (int c0 = beg; c0 < end; c0 += 128) {
            int m = end - c0; if (m > 128) m = 128;
            __syncthreads();
            if (t < m) { ss[t] = g_csrc[c0 + t] * 128; sw[t] = g_cw[c0 + t]; }
            __syncthreads();
            int e = 0;
            for (; e + 4 <= m; e += 4) {
                float2 v0 = __half22float2(__ldg(X + ss[e + 0] + t));
                float2 v1 = __half22float2(__ldg(X + ss[e + 1] + t));
                float2 v2 = __half22float2(__ldg(X + ss[e + 2] + t));
                float2 v3 = __half22float2(__ldg(X + ss[e + 3] + t));
                a0 += sw[e + 0] * v0.x + sw[e + 1] * v1.x + sw[e + 2] * v2.x + sw[e + 3] * v3.x;
                a1 += sw[e + 0] * v0.y + sw[e + 1] * v1.y + sw[e + 2] * v2.y + sw[e + 3] * v3.y;
            }
            for (; e < m; e++) {
                float2 v = __half22float2(__ldg(X + ss[e] + t));
                a0 += sw[e] * v.x;
                a1 += sw[e] * v.y;
            }
        }
        float2 self = __half22float2(X[(size_t)i * 128 + t]);
        float h0 = fmaxf(d * a0 + d * d * self.x + bb, 0.f);
        float h1 = fmaxf(d * a1 + d * d * self.y + bb, 0.f);
        float sI = d * (g_tsum[i] + d);
        acc0 += sI * h0;
        acc1 += sI * h1;
    }
    int ci = (blockIdx.x & (NC - 1)) * 256;
    atomicAdd(&g_acc[ci + t], acc0);
    atomicAdd(&g_acc[ci + 128 + t], acc1);
}

// -------- final: out[b][h2] = b2 + (1/N) * v[b] @ W2 --------
__global__ void k_final(const float* __restrict__ W2, const float* __restrict__ b2,
                        float* __restrict__ out) {
    __shared__ float v[256];
    int t = threadIdx.x;
    float s = 0.f;
    for (int c = 0; c < NC; c++) s += g_acc[c * 256 + t];
    v[t] = s * (1.0f / (float)Nn);
    __syncthreads();
    int b = t >> 7, h2 = t & 127;
    float o = b2[h2];
    for (int f = 0; f < 128; f++) o += v[b * 128 + f] * W2[f * Hh + h2];
    out[b * Hh + h2] = o;
}

extern "C" void kernel_launch(void* const* d_in, const int* in_sizes, int n_in,
                              void* d_out, int out_size) {
    const float* node  = (const float*)d_in[0];
    const int*   ntype = (const int*)d_in[1];
    const int*   ei    = (const int*)d_in[2];
    const float* embed = (const float*)d_in[3];
    const float* W1    = (const float*)d_in[4];
    const float* b1    = (const float*)d_in[5];
    const float* W2    = (const float*)d_in[6];
    const float* b2    = (const float*)d_in[7];
    const int* src = ei;
    const int* dst = ei + Ee;

    k_zero<<<256, 256>>>();
    k_hist<<<1024, 256>>>(dst);
    k_dis<<<(Nn + 255) / 256, 256>>>();
    k_scanA<<<NSB, 1024>>>();
    k_scanB<<<1, 32>>>();
    k_scanC<<<NSB, 1024>>>();
    k_scatter<<<1024, 256>>>(src, dst);
    k_embtab<<<4, 256>>>(embed, W1);
    k_wsplit<<<(64 * Hh + 255) / 256, 256>>>(W1);
    k_gemm<<<dim3((Nn + 127) / 128, Bb), 256>>>(node, ntype);
    k_agg<<<(Nn + NPB - 1) / NPB, 128>>>(b1);
    k_final<<<1, 256>>>(W2, b2, (float*)d_out);
}

// round 10
// speedup vs baseline: 2.4146x; 1.0254x over previous
#include <cuda_runtime.h>
#include <cuda_fp16.h>
#include <cuda_bf16.h>
#include <cstdint>

#define Nn   100000
#define Ee   1600000
#define Bb   2
#define FIN  116
#define EMBD 12
#define Hh   128
#define NS2  8           // K chunks of 16 (K padded to 128)
#define NC   128         // accumulator copies
#define NPB  16          // nodes per agg block
#define NSB  98          // scan blocks (ceil(100000/1024))

#define QSCALE (127.0f / 8.0f)
#define QINV   (8.0f / 127.0f)

// -------- scratch (static device globals) --------
__device__ char  g_x8[(size_t)Nn * 256];   // [n][2h+b] int8 quantized xw1: 25.6 MB (L2-resident)
__device__ int   g_cnt[Nn];
__device__ int   g_cursor[Nn];
__device__ float g_dis[Nn];
__device__ float g_tsum[Nn];
__device__ int   g_rowstart[Nn + 1];
__device__ int   g_bsum[NSB];
__device__ int   g_csrc[Ee];
__device__ float g_T[8 * Hh];
__device__ float g_acc[NC * 256];
__device__ uint32_t g_W1p[2][64][Hh];  // [split hi/lo][kpair][h] bf16x2 packed

// -------- small helpers --------
__device__ __forceinline__ uint32_t packbf(float lo, float hi) {
    uint32_t r; asm("cvt.rn.bf16x2.f32 %0, %1, %2;" : "=r"(r) : "f"(hi), "f"(lo)); return r;
}
__device__ __forceinline__ void cp4(uint32_t dst, const void* src, bool pred) {
    int sz = pred ? 4 : 0;
    asm volatile("cp.async.ca.shared.global [%0], [%1], 4, %2;\n" :: "r"(dst), "l"(src), "r"(sz));
}
#define CP_COMMIT() asm volatile("cp.async.commit_group;\n" ::: "memory")
#define CP_WAIT1()  asm volatile("cp.async.wait_group 1;\n" ::: "memory")

#define MMA_BF16(Cr, Ar, B0, B1)                                              \
    asm volatile("mma.sync.aligned.m16n8k16.row.col.f32.bf16.bf16.f32 "       \
                 "{%0,%1,%2,%3},{%4,%5,%6,%7},{%8,%9},{%0,%1,%2,%3};"         \
                 : "+f"(Cr[0]), "+f"(Cr[1]), "+f"(Cr[2]), "+f"(Cr[3])         \
                 : "r"(Ar[0]), "r"(Ar[1]), "r"(Ar[2]), "r"(Ar[3]),            \
                   "r"(B0), "r"(B1))

__device__ __forceinline__ char quant8(float v) {
    int q = __float2int_rn(v * QSCALE);
    q = max(-127, min(127, q));
    return (char)q;
}

// -------- prep kernels --------
__global__ void k_zero() {
    int i = blockIdx.x * blockDim.x + threadIdx.x;
    int stride = gridDim.x * blockDim.x;
    for (int j = i; j < Nn; j += stride) { g_cnt[j] = 0; g_cursor[j] = 0; g_tsum[j] = 0.f; }
    for (int j = i; j < NC * 256; j += stride) g_acc[j] = 0.f;
}

__global__ void k_hist(const int* __restrict__ dst) {
    int i = blockIdx.x * blockDim.x + threadIdx.x;
    int stride = gridDim.x * blockDim.x;
    for (int e = i; e < Ee; e += stride) atomicAdd(&g_cnt[dst[e]], 1);
}

// ---- 3-phase parallel scan; phase A also computes dis = rsqrt(deg+1) ----
__global__ void k_scanA() {
    __shared__ int sd[1024];
    int t = threadIdx.x;
    int idx = blockIdx.x * 1024 + t;
    int v = (idx < Nn) ? g_cnt[idx] : 0;
    sd[t] = v;
    __syncthreads();
    for (int off = 1; off < 1024; off <<= 1) {
        int x = (t >= off) ? sd[t - off] : 0;
        __syncthreads();
        sd[t] += x;
        __syncthreads();
    }
    if (idx < Nn) {
        g_rowstart[idx] = sd[t] - v;   // block-local exclusive
        g_dis[idx] = rsqrtf((float)v + 1.0f);
    }
    if (t == 1023) g_bsum[blockIdx.x] = sd[1023];
}

__global__ void k_scanB() {
    if (threadIdx.x == 0) {
        int c = 0;
        for (int i = 0; i < NSB; i++) { int v = g_bsum[i]; g_bsum[i] = c; c += v; }
        g_rowstart[Nn] = c;
    }
}

__global__ void k_scanC() {
    int t = threadIdx.x;
    int idx = blockIdx.x * 1024 + t;
    if (idx < Nn) g_rowstart[idx] += g_bsum[blockIdx.x];
}

// scatter (CSR col indices) + fused tsum accumulation
__global__ void k_scatter(const int* __restrict__ src, const int* __restrict__ dst) {
    int i = blockIdx.x * blockDim.x + threadIdx.x;
    int stride = gridDim.x * blockDim.x;
    for (int e = i; e < Ee; e += stride) {
        int d = dst[e], s = src[e];
        int pos = g_rowstart[d] + atomicAdd(&g_cursor[d], 1);
        g_csrc[pos] = s;
        atomicAdd(&g_tsum[s], g_dis[d]);
    }
}

// fused: W1 bf16 hi/lo split pack (idx < 64*128) + embed table (next 1024)
__global__ void k_prep(const float* __restrict__ W1, const float* __restrict__ embed) {
    int idx = blockIdx.x * blockDim.x + threadIdx.x;
    if (idx < 64 * Hh) {
        int kp = idx >> 7, h = idx & 127;
        int k0 = 2 * kp, k1 = 2 * kp + 1;
        float w0 = (k0 < FIN) ? W1[k0 * Hh + h] : 0.f;
        float w1 = (k1 < FIN) ? W1[k1 * Hh + h] : 0.f;
        float h0 = __bfloat162float(__float2bfloat16(w0));
        float h1 = __bfloat162float(__float2bfloat16(w1));
        g_W1p[0][kp][h] = packbf(h0, h1);
        g_W1p[1][kp][h] = packbf(w0 - h0, w1 - h1);
    } else if (idx < 64 * Hh + 8 * Hh) {
        int j2 = idx - 64 * Hh;
        int e = j2 >> 7, h = j2 & 127;
        float s = 0.f;
        #pragma unroll
        for (int j = 0; j < EMBD; j++) s += embed[e * EMBD + j] * W1[(FIN + j) * Hh + h];
        g_T[j2] = s;
    }
}

// -------- bf16 tensor-core GEMM: xw1 = x @ W1 (split-B hi/lo), epilogue adds embed term, stores int8 --------
__global__ __launch_bounds__(256, 2) void k_gemm(const float* __restrict__ node,
                                                 const int* __restrict__ ntype) {
    __shared__ float    As[2][16][137];
    __shared__ uint32_t Bp[2][2][8][136];   // [buf][split][kpair][h]
    int b = blockIdx.y;
    int n0 = blockIdx.x * 128;
    int t = threadIdx.x;
    int w = t >> 5, lane = t & 31;
    int wm = w & 3, wn = w >> 2;         // warp tile: rows wm*32, cols wn*64
    int g = lane >> 2, t4 = lane & 3;
    const float* Abase = node + (size_t)b * Nn * FIN;

    uint32_t sAs = (uint32_t)__cvta_generic_to_shared(&As[0][0][0]);
    uint32_t sBp = (uint32_t)__cvta_generic_to_shared(&Bp[0][0][0][0]);

    float C[2][8][4];
    #pragma unroll
    for (int mt = 0; mt < 2; mt++)
        #pragma unroll
        for (int nt = 0; nt < 8; nt++)
            #pragma unroll
            for (int x = 0; x < 4; x++) C[mt][nt][x] = 0.f;

    auto issue = [&](int s) {
        int k0 = s * 16;
        int buf = s & 1;
        #pragma unroll
        for (int i = 0; i < 8; i++) {
            int lin = i * 256 + t;
            int row = lin >> 4, kk = lin & 15;
            int n = n0 + row, k = k0 + kk;
            bool ok = (n < Nn) && (k < FIN);
            const float* srcp = ok ? (Abase + (size_t)n * FIN + k) : Abase;
            cp4(sAs + (((buf * 16 + kk) * 137 + row) << 2), srcp, ok);
        }
        #pragma unroll
        for (int i = 0; i < 8; i++) {
            int lin = i * 256 + t;
            int h = lin & 127;
            int kp = (lin >> 7) & 7;
            int sp = lin >> 10;
            cp4(sBp + ((((buf * 2 + sp) * 8 + kp) * 136 + h) << 2),
                &g_W1p[sp][s * 8 + kp][h], true);
        }
    };

    issue(0);
    CP_COMMIT();

    for (int s = 0; s < NS2; s++) {
        if (s + 1 < NS2) issue(s + 1);
        CP_COMMIT();
        CP_WAIT1();
        __syncthreads();
        int buf = s & 1;

        uint32_t a[2][4];
        #pragma unroll
        for (int mt = 0; mt < 2; mt++) {
            int R = wm * 32 + mt * 16;
            a[mt][0] = packbf(As[buf][2 * t4][R + g],     As[buf][2 * t4 + 1][R + g]);
            a[mt][1] = packbf(As[buf][2 * t4][R + g + 8], As[buf][2 * t4 + 1][R + g + 8]);
            a[mt][2] = packbf(As[buf][2 * t4 + 8][R + g],     As[buf][2 * t4 + 9][R + g]);
            a[mt][3] = packbf(As[buf][2 * t4 + 8][R + g + 8], As[buf][2 * t4 + 9][R + g + 8]);
        }
        #pragma unroll
        for (int nt = 0; nt < 8; nt++) {
            int c = wn * 64 + nt * 8 + g;
            uint32_t bh0 = Bp[buf][0][t4][c];
            uint32_t bh1 = Bp[buf][0][t4 + 4][c];
            uint32_t bl0 = Bp[buf][1][t4][c];
            uint32_t bl1 = Bp[buf][1][t4 + 4][c];
            MMA_BF16(C[0][nt], a[0], bh0, bh1);
            MMA_BF16(C[1][nt], a[1], bh0, bh1);
            MMA_BF16(C[0][nt], a[0], bl0, bl1);
            MMA_BF16(C[1][nt], a[1], bl0, bl1);
        }
        __syncthreads();
    }

    // epilogue: add embed-table term, quantize to int8 at [n][2h+b]
    #pragma unroll
    for (int mt = 0; mt < 2; mt++) {
        int r0 = n0 + wm * 32 + mt * 16 + g;
        int r1 = r0 + 8;
        int e0 = (r0 < Nn) ? ntype[r0] : 0;
        int e1 = (r1 < Nn) ? ntype[r1] : 0;
        #pragma unroll
        for (int nt = 0; nt < 8; nt++) {
            int h = wn * 64 + nt * 8 + 2 * t4;
            if (r0 < Nn) {
                g_x8[(size_t)r0 * 256 + 2 * h + b]       = quant8(C[mt][nt][0] + g_T[e0 * Hh + h]);
                g_x8[(size_t)r0 * 256 + 2 * (h + 1) + b] = quant8(C[mt][nt][1] + g_T[e0 * Hh + h + 1]);
            }
            if (r1 < Nn) {
                g_x8[(size_t)r1 * 256 + 2 * h + b]       = quant8(C[mt][nt][2] + g_T[e1 * Hh + h]);
                g_x8[(size_t)r1 * 256 + 2 * (h + 1) + b] = quant8(C[mt][nt][3] + g_T[e1 * Hh + h + 1]);
            }
        }
    }
}

// -------- aggregation: 16 nodes per block, 128 threads (feature t, both batches via char2) --------
__global__ __launch_bounds__(128) void k_agg(const float* __restrict__ b1) {
    int i0 = blockIdx.x * NPB;
    int t = threadIdx.x;
    __shared__ int   ss[128];
    __shared__ float sw[128];
    const char2* X = (const char2*)g_x8;
    float bb = b1[t];
    float acc0 = 0.f, acc1 = 0.f;
    int iend = i0 + NPB; if (iend > Nn) iend = Nn;

    for (int i = i0; i < iend; i++) {
        int beg = g_rowstart[i], end = g_rowstart[i + 1];
        float d = g_dis[i];
        float a0 = 0.f, a1 = 0.f;
        for (int c0 = beg; c0 < end; c0 += 128) {
            int m = end - c0; if (m > 128) m = 128;
            __syncthreads();
            if (t < m) { int s = g_csrc[c0 + t]; ss[t] = s * 128; sw[t] = g_dis[s]; }
            __syncthreads();
            int e = 0;
            for (; e + 4 <= m; e += 4) {
                char2 v0 = __ldg(X + ss[e + 0] + t);
                char2 v1 = __ldg(X + ss[e + 1] + t);
                char2 v2 = __ldg(X + ss[e + 2] + t);
                char2 v3 = __ldg(X + ss[e + 3] + t);
                a0 += sw[e + 0] * (float)v0.x + sw[e + 1] * (float)v1.x
                    + sw[e + 2] * (float)v2.x + sw[e + 3] * (float)v3.x;
                a1 += sw[e + 0] * (float)v0.y + sw[e + 1] * (float)v1.y
                    + sw[e + 2] * (float)v2.y + sw[e + 3] * (float)v3.y;
            }
            for (; e < m; e++) {
                char2 v = __ldg(X + ss[e] + t);
                a0 += sw[e] * (float)v.x;
                a1 += sw[e] * (float)v.y;
            }
        }
        char2 self = X[(size_t)i * 128 + t];
        float h0 = fmaxf(QINV * d * (a0 + d * (float)self.x) + bb, 0.f);
        float h1 = fmaxf(QINV * d * (a1 + d * (float)self.y) + bb, 0.f);
        float sI = d * (g_tsum[i] + d);
        acc0 += sI * h0;
        acc1 += sI * h1;
    }
    int ci = (blockIdx.x & (NC - 1)) * 256;
    atomicAdd(&g_acc[ci + t], acc0);
    atomicAdd(&g_acc[ci + 128 + t], acc1);
}

// -------- final: out[b][h2] = b2 + (1/N) * v[b] @ W2 --------
__global__ void k_final(const float* __restrict__ W2, const float* __restrict__ b2,
                        float* __restrict__ out) {
    __shared__ float v[256];
    int t = threadIdx.x;
    float s = 0.f;
    for (int c = 0; c < NC; c++) s += g_acc[c * 256 + t];
    v[t] = s * (1.0f / (float)Nn);
    __syncthreads();
    int b = t >> 7, h2 = t & 127;
    float o = b2[h2];
    for (int f = 0; f < 128; f++) o += v[b * 128 + f] * W2[f * Hh + h2];
    out[b * Hh + h2] = o;
}

extern "C" void kernel_launch(void* const* d_in, const int* in_sizes, int n_in,
                              void* d_out, int out_size) {
    const float* node  = (const float*)d_in[0];
    const int*   ntype = (const int*)d_in[1];
    const int*   ei    = (const int*)d_in[2];
    const float* embed = (const float*)d_in[3];
    const float* W1    = (const float*)d_in[4];
    const float* b1    = (const float*)d_in[5];
    const float* W2    = (const float*)d_in[6];
    const float* b2    = (const float*)d_in[7];
    const int* src = ei;
    const int* dst = ei + Ee;

    k_zero<<<256, 256>>>();
    k_hist<<<1024, 256>>>(dst);
    k_scanA<<<NSB, 1024>>>();
    k_scanB<<<1, 32>>>();
    k_scanC<<<NSB, 1024>>>();
    k_scatter<<<1024, 256>>>(src, dst);
    k_prep<<<(64 * Hh + 8 * Hh + 255) / 256, 256>>>(W1, embed);
    k_gemm<<<dim3((Nn + 127) / 128, Bb), 256>>>(node, ntype);
    k_agg<<<(Nn + NPB - 1) / NPB, 128>>>(b1);
    k_final<<<1, 256>>>(W2, b2, (float*)d_out);
}

// round 12
// speedup vs baseline: 3.0028x; 1.2436x over previous
#include <cuda_runtime.h>
#include <cuda_fp16.h>
#include <cuda_bf16.h>
#include <cstdint>

#define Nn   100000
#define Ee   1600000
#define Bb   2
#define FIN  116
#define EMBD 12
#define Hh   128
#define NS2  8           // K chunks of 16 (K padded to 128)
#define NC   128         // accumulator copies
#define NPB  64          // nodes per agg block (16 per warp)
#define NSB  98          // scan blocks (ceil(100000/1024))

#define QSCALE (127.0f / 8.0f)
#define QINV   (8.0f / 127.0f)

// -------- scratch (static device globals) --------
__device__ char  g_x8[(size_t)Nn * 256];   // [n][2h+b] int8 quantized xw1: 25.6 MB
__device__ int   g_cnt[Nn];
__device__ int   g_cursor[Nn];
__device__ float g_dis[Nn];
__device__ float g_tsum[Nn];
__device__ int   g_rowstart[Nn + 1];
__device__ int   g_bsum[NSB];
__device__ int   g_csrc[Ee];               // bits[0:17)=src, bits[17:32)=u15 dis[src]
__device__ float g_T[8 * Hh];
__device__ float g_acc[NC * 256];
__device__ uint32_t g_W1p[2][64][Hh];      // [split hi/lo][kpair][h] bf16x2 packed

// -------- small helpers --------
__device__ __forceinline__ uint32_t packbf(float lo, float hi) {
    uint32_t r; asm("cvt.rn.bf16x2.f32 %0, %1, %2;" : "=r"(r) : "f"(hi), "f"(lo)); return r;
}
__device__ __forceinline__ void cp16(uint32_t dst, const void* src, bool pred) {
    int sz = pred ? 16 : 0;
    asm volatile("cp.async.cg.shared.global [%0], [%1], 16, %2;\n" :: "r"(dst), "l"(src), "r"(sz));
}
#define CP_COMMIT() asm volatile("cp.async.commit_group;\n" ::: "memory")
#define CP_WAIT1()  asm volatile("cp.async.wait_group 1;\n" ::: "memory")

#define MMA_BF16(Cr, Ar, B0, B1)                                              \
    asm volatile("mma.sync.aligned.m16n8k16.row.col.f32.bf16.bf16.f32 "       \
                 "{%0,%1,%2,%3},{%4,%5,%6,%7},{%8,%9},{%0,%1,%2,%3};"         \
                 : "+f"(Cr[0]), "+f"(Cr[1]), "+f"(Cr[2]), "+f"(Cr[3])         \
                 : "r"(Ar[0]), "r"(Ar[1]), "r"(Ar[2]), "r"(Ar[3]),            \
                   "r"(B0), "r"(B1))

__device__ __forceinline__ char quant8(float v) {
    int q = __float2int_rn(v * QSCALE);
    q = max(-127, min(127, q));
    return (char)q;
}
__device__ __forceinline__ __half2 u2h2(uint32_t u) {
    __half2_raw r; r.x = (unsigned short)(u & 0xffff); r.y = (unsigned short)(u >> 16);
    return r;
}

// -------- prep kernels --------
__global__ void k_zero() {
    int i = blockIdx.x * blockDim.x + threadIdx.x;
    int stride = gridDim.x * blockDim.x;
    for (int j = i; j < Nn; j += stride) { g_cnt[j] = 0; g_cursor[j] = 0; g_tsum[j] = 0.f; }
    for (int j = i; j < NC * 256; j += stride) g_acc[j] = 0.f;
}

__global__ void k_hist(const int* __restrict__ dst) {
    int i = blockIdx.x * blockDim.x + threadIdx.x;
    int stride = gridDim.x * blockDim.x;
    for (int e = i; e < Ee; e += stride) atomicAdd(&g_cnt[dst[e]], 1);
}

// ---- 3-phase parallel scan; phase A also computes dis = rsqrt(deg+1) ----
__global__ void k_scanA() {
    __shared__ int sd[1024];
    int t = threadIdx.x;
    int idx = blockIdx.x * 1024 + t;
    int v = (idx < Nn) ? g_cnt[idx] : 0;
    sd[t] = v;
    __syncthreads();
    for (int off = 1; off < 1024; off <<= 1) {
        int x = (t >= off) ? sd[t - off] : 0;
        __syncthreads();
        sd[t] += x;
        __syncthreads();
    }
    if (idx < Nn) {
        g_rowstart[idx] = sd[t] - v;   // block-local exclusive
        g_dis[idx] = rsqrtf((float)v + 1.0f);
    }
    if (t == 1023) g_bsum[blockIdx.x] = sd[1023];
}

// warp-parallel scan of the 98 block sums
__global__ void k_scanB() {
    int l = threadIdx.x;   // 32 threads
    int base = 4 * l;
    int v0 = (base + 0 < NSB) ? g_bsum[base + 0] : 0;
    int v1 = (base + 1 < NSB) ? g_bsum[base + 1] : 0;
    int v2 = (base + 2 < NSB) ? g_bsum[base + 2] : 0;
    int v3 = (base + 3 < NSB) ? g_bsum[base + 3] : 0;
    int t0 = v0, t1 = t0 + v1, t2 = t1 + v2, tot = t2 + v3;
    int incl = tot;
    #pragma unroll
    for (int off = 1; off < 32; off <<= 1) {
        int y = __shfl_up_sync(0xffffffffu, incl, off);
        if (l >= off) incl += y;
    }
    int excl = incl - tot;
    if (base + 0 < NSB) g_bsum[base + 0] = excl;
    if (base + 1 < NSB) g_bsum[base + 1] = excl + t0;
    if (base + 2 < NSB) g_bsum[base + 2] = excl + t1;
    if (base + 3 < NSB) g_bsum[base + 3] = excl + t2;
    if (l == 31) g_rowstart[Nn] = incl;
}

__global__ void k_scanC() {
    int t = threadIdx.x;
    int idx = blockIdx.x * 1024 + t;
    if (idx < Nn) g_rowstart[idx] += g_bsum[blockIdx.x];
}

// scatter CSR col (src + packed u15 dis[src]) + fused tsum accumulation
__global__ void k_scatter(const int* __restrict__ src, const int* __restrict__ dst) {
    int i = blockIdx.x * blockDim.x + threadIdx.x;
    int stride = gridDim.x * blockDim.x;
    for (int e = i; e < Ee; e += stride) {
        int d = dst[e], s = src[e];
        int pos = g_rowstart[d] + atomicAdd(&g_cursor[d], 1);
        float ds = g_dis[s];
        int q = (int)(ds * 32767.0f + 0.5f);
        g_csrc[pos] = s | (q << 17);
        atomicAdd(&g_tsum[s], g_dis[d]);
    }
}

// fused: W1 bf16 hi/lo split pack + embed table
__global__ void k_prep(const float* __restrict__ W1, const float* __restrict__ embed) {
    int idx = blockIdx.x * blockDim.x + threadIdx.x;
    if (idx < 64 * Hh) {
        int kp = idx >> 7, h = idx & 127;
        int k0 = 2 * kp, k1 = 2 * kp + 1;
        float w0 = (k0 < FIN) ? W1[k0 * Hh + h] : 0.f;
        float w1 = (k1 < FIN) ? W1[k1 * Hh + h] : 0.f;
        float h0 = __bfloat162float(__float2bfloat16(w0));
        float h1 = __bfloat162float(__float2bfloat16(w1));
        g_W1p[0][kp][h] = packbf(h0, h1);
        g_W1p[1][kp][h] = packbf(w0 - h0, w1 - h1);
    } else if (idx < 64 * Hh + 8 * Hh) {
        int j2 = idx - 64 * Hh;
        int e = j2 >> 7, h = j2 & 127;
        float s = 0.f;
        #pragma unroll
        for (int j = 0; j < EMBD; j++) s += embed[e * EMBD + j] * W1[(FIN + j) * Hh + h];
        g_T[j2] = s;
    }
}

// -------- bf16 tensor-core GEMM (split-B hi/lo), float4 cp.async staging, int8 store --------
__global__ __launch_bounds__(256, 2) void k_gemm(const float* __restrict__ node,
                                                 const int* __restrict__ ntype) {
    __shared__ float    As[2][128][20];     // [buf][row][k] (+4 pad)
    __shared__ uint32_t Bp[2][2][8][136];   // [buf][split][kpair][h]
    int b = blockIdx.y;
    int n0 = blockIdx.x * 128;
    int t = threadIdx.x;
    int w = t >> 5, lane = t & 31;
    int wm = w & 3, wn = w >> 2;         // warp tile: rows wm*32, cols wn*64
    int g = lane >> 2, t4 = lane & 3;
    const float* Abase = node + (size_t)b * Nn * FIN;

    uint32_t sAs = (uint32_t)__cvta_generic_to_shared(&As[0][0][0]);
    uint32_t sBp = (uint32_t)__cvta_generic_to_shared(&Bp[0][0][0][0]);

    float C[2][8][4];
    #pragma unroll
    for (int mt = 0; mt < 2; mt++)
        #pragma unroll
        for (int nt = 0; nt < 8; nt++)
            #pragma unroll
            for (int x = 0; x < 4; x++) C[mt][nt][x] = 0.f;

    auto issue = [&](int s) {
        int buf = s & 1;
        // A: 128 rows x 4 float4 = 512 f4, 2 per thread
        #pragma unroll
        for (int i = 0; i < 2; i++) {
            int lin = i * 256 + t;
            int row = lin >> 2, c = lin & 3;
            int n = n0 + row, k = s * 16 + 4 * c;
            bool ok = (n < Nn) && (k < FIN);
            const float* srcp = ok ? (Abase + (size_t)n * FIN + k) : Abase;
            cp16(sAs + (((buf * 128 + row) * 20 + 4 * c) << 2), srcp, ok);
        }
        // B: 2 splits x 8 kpairs x 32 f4 = 512 f4, 2 per thread
        #pragma unroll
        for (int i = 0; i < 2; i++) {
            int lin = i * 256 + t;
            int c = lin & 31, kp = (lin >> 5) & 7, sp = lin >> 8;
            cp16(sBp + ((((buf * 2 + sp) * 8 + kp) * 136 + 4 * c) << 2),
                 &g_W1p[sp][s * 8 + kp][4 * c], true);
        }
    };

    issue(0);
    CP_COMMIT();

    for (int s = 0; s < NS2; s++) {
        if (s + 1 < NS2) issue(s + 1);
        CP_COMMIT();
        CP_WAIT1();
        __syncthreads();
        int buf = s & 1;

        uint32_t a[2][4];
        #pragma unroll
        for (int mt = 0; mt < 2; mt++) {
            int R = wm * 32 + mt * 16;
            float2 v0 = *(const float2*)&As[buf][R + g][2 * t4];
            float2 v1 = *(const float2*)&As[buf][R + g + 8][2 * t4];
            float2 v2 = *(const float2*)&As[buf][R + g][2 * t4 + 8];
            float2 v3 = *(const float2*)&As[buf][R + g + 8][2 * t4 + 8];
            a[mt][0] = packbf(v0.x, v0.y);
            a[mt][1] = packbf(v1.x, v1.y);
            a[mt][2] = packbf(v2.x, v2.y);
            a[mt][3] = packbf(v3.x, v3.y);
        }
        #pragma unroll
        for (int nt = 0; nt < 8; nt++) {
            int c = wn * 64 + nt * 8 + g;
            uint32_t bh0 = Bp[buf][0][t4][c];
            uint32_t bh1 = Bp[buf][0][t4 + 4][c];
            uint32_t bl0 = Bp[buf][1][t4][c];
            uint32_t bl1 = Bp[buf][1][t4 + 4][c];
            MMA_BF16(C[0][nt], a[0], bh0, bh1);
            MMA_BF16(C[1][nt], a[1], bh0, bh1);
            MMA_BF16(C[0][nt], a[0], bl0, bl1);
            MMA_BF16(C[1][nt], a[1], bl0, bl1);
        }
        __syncthreads();
    }

    // epilogue: add embed-table term, quantize to int8 at [n][2h+b]
    #pragma unroll
    for (int mt = 0; mt < 2; mt++) {
        int r0 = n0 + wm * 32 + mt * 16 + g;
        int r1 = r0 + 8;
        int e0 = (r0 < Nn) ? ntype[r0] : 0;
        int e1 = (r1 < Nn) ? ntype[r1] : 0;
        #pragma unroll
        for (int nt = 0; nt < 8; nt++) {
            int h = wn * 64 + nt * 8 + 2 * t4;
            if (r0 < Nn) {
                g_x8[(size_t)r0 * 256 + 2 * h + b]       = quant8(C[mt][nt][0] + g_T[e0 * Hh + h]);
                g_x8[(size_t)r0 * 256 + 2 * (h + 1) + b] = quant8(C[mt][nt][1] + g_T[e0 * Hh + h + 1]);
            }
            if (r1 < Nn) {
                g_x8[(size_t)r1 * 256 + 2 * h + b]       = quant8(C[mt][nt][2] + g_T[e1 * Hh + h]);
                g_x8[(size_t)r1 * 256 + 2 * (h + 1) + b] = quant8(C[mt][nt][3] + g_T[e1 * Hh + h + 1]);
            }
        }
    }
}

// -------- aggregation: warp-per-node, 1 LDG.64 per edge, half2 math --------
__device__ __forceinline__ void agg_edge(int2 v, __half2 W, __half2 HB, __half2 acc[4]) {
    uint32_t x0 = (uint32_t)v.x ^ 0x80808080u;
    uint32_t x1 = (uint32_t)v.y ^ 0x80808080u;
    acc[0] = __hfma2(__hsub2(u2h2(__byte_perm(x0, 0x64646464u, 0x5140)), HB), W, acc[0]);
    acc[1] = __hfma2(__hsub2(u2h2(__byte_perm(x0, 0x64646464u, 0x7362)), HB), W, acc[1]);
    acc[2] = __hfma2(__hsub2(u2h2(__byte_perm(x1, 0x64646464u, 0x5140)), HB), W, acc[2]);
    acc[3] = __hfma2(__hsub2(u2h2(__byte_perm(x1, 0x64646464u, 0x7362)), HB), W, acc[3]);
}

__global__ __launch_bounds__(128) void k_agg(const float* __restrict__ b1) {
    int w = threadIdx.x >> 5, l = threadIdx.x & 31;
    int ibase = blockIdx.x * NPB + w * 16;
    int ilim = ibase + 16; if (ilim > Nn) ilim = Nn;
    const float4 bb = ((const float4*)b1)[l];     // b1[4l .. 4l+3]
    const __half2 HB = u2h2(0x64806480u);
    float2 facc[4] = {{0.f,0.f},{0.f,0.f},{0.f,0.f},{0.f,0.f}};

    for (int i = ibase; i < ilim; i++) {
        int beg = g_rowstart[i], end = g_rowstart[i + 1];
        __half2 acc[4];
        acc[0] = acc[1] = acc[2] = acc[3] = u2h2(0u);
        for (int c = beg; c < end; c += 32) {
            int m = end - c; if (m > 32) m = 32;
            int wd = (l < m) ? __ldg(&g_csrc[c + l]) : 0;
            int j = 0;
            for (; j + 4 <= m; j += 4) {
                int e0 = __shfl_sync(0xffffffffu, wd, j);
                int e1 = __shfl_sync(0xffffffffu, wd, j + 1);
                int e2 = __shfl_sync(0xffffffffu, wd, j + 2);
                int e3 = __shfl_sync(0xffffffffu, wd, j + 3);
                int2 v0 = __ldg((const int2*)(g_x8 + (size_t)(e0 & 0x1ffff) * 256) + l);
                int2 v1 = __ldg((const int2*)(g_x8 + (size_t)(e1 & 0x1ffff) * 256) + l);
                int2 v2 = __ldg((const int2*)(g_x8 + (size_t)(e2 & 0x1ffff) * 256) + l);
                int2 v3 = __ldg((const int2*)(g_x8 + (size_t)(e3 & 0x1ffff) * 256) + l);
                __half2 W0 = __float2half2_rn((float)((uint32_t)e0 >> 17) * (1.0f / 32767.0f));
                __half2 W1_ = __float2half2_rn((float)((uint32_t)e1 >> 17) * (1.0f / 32767.0f));
                __half2 W2_ = __float2half2_rn((float)((uint32_t)e2 >> 17) * (1.0f / 32767.0f));
                __half2 W3 = __float2half2_rn((float)((uint32_t)e3 >> 17) * (1.0f / 32767.0f));
                agg_edge(v0, W0, HB, acc);
                agg_edge(v1, W1_, HB, acc);
                agg_edge(v2, W2_, HB, acc);
                agg_edge(v3, W3, HB, acc);
            }
            for (; j < m; j++) {
                int e0 = __shfl_sync(0xffffffffu, wd, j);
                int2 v0 = __ldg((const int2*)(g_x8 + (size_t)(e0 & 0x1ffff) * 256) + l);
                __half2 W0 = __float2half2_rn((float)((uint32_t)e0 >> 17) * (1.0f / 32767.0f));
                agg_edge(v0, W0, HB, acc);
            }
        }
        // self term + epilogue
        int2 vs = __ldg((const int2*)(g_x8 + (size_t)i * 256) + l);
        __half2 sf[4];
        sf[0] = sf[1] = sf[2] = sf[3] = u2h2(0u);
        agg_edge(vs, __float2half2_rn(1.0f), HB, sf);
        float d = g_dis[i];
        float sI = d * (g_tsum[i] + d);
        float qd = QINV * d;
        const float* bbp = (const float*)&bb;
        #pragma unroll
        for (int k = 0; k < 4; k++) {
            float2 a2 = __half22float2(acc[k]);
            float2 s2 = __half22float2(sf[k]);
            float h0 = fmaxf(fmaf(qd, a2.x + d * s2.x, bbp[k]), 0.f);
            float h1 = fmaxf(fmaf(qd, a2.y + d * s2.y, bbp[k]), 0.f);
            facc[k].x += sI * h0;
            facc[k].y += sI * h1;
        }
    }
    int ci = ((blockIdx.x << 2) + w) & (NC - 1);
    float* dst = g_acc + ci * 256;
    #pragma unroll
    for (int k = 0; k < 4; k++) {
        atomicAdd(dst + 4 * l + k, facc[k].x);         // batch 0
        atomicAdd(dst + 128 + 4 * l + k, facc[k].y);   // batch 1
    }
}

// -------- final: out[b][h2] = b2 + (1/N) * v[b] @ W2 --------
__global__ void k_final(const float* __restrict__ W2, const float* __restrict__ b2,
                        float* __restrict__ out) {
    __shared__ float v[256];
    int t = threadIdx.x;
    float s = 0.f;
    for (int c = 0; c < NC; c++) s += g_acc[c * 256 + t];
    v[t] = s * (1.0f / (float)Nn);
    __syncthreads();
    int b = t >> 7, h2 = t & 127;
    float o = b2[h2];
    for (int f = 0; f < 128; f++) o += v[b * 128 + f] * W2[f * Hh + h2];
    out[b * Hh + h2] = o;
}

extern "C" void kernel_launch(void* const* d_in, const int* in_sizes, int n_in,
                              void* d_out, int out_size) {
    const float* node  = (const float*)d_in[0];
    const int*   ntype = (const int*)d_in[1];
    const int*   ei    = (const int*)d_in[2];
    const float* embed = (const float*)d_in[3];
    const float* W1    = (const float*)d_in[4];
    const float* b1    = (const float*)d_in[5];
    const float* W2    = (const float*)d_in[6];
    const float* b2    = (const float*)d_in[7];
    const int* src = ei;
    const int* dst = ei + Ee;

    k_zero<<<256, 256>>>();
    k_hist<<<1024, 256>>>(dst);
    k_scanA<<<NSB, 1024>>>();
    k_scanB<<<1, 32>>>();
    k_scanC<<<NSB, 1024>>>();
    k_scatter<<<1024, 256>>>(src, dst);
    k_prep<<<(64 * Hh + 8 * Hh + 255) / 256, 256>>>(W1, embed);
    k_gemm<<<dim3((Nn + 127) / 128, Bb), 256>>>(node, ntype);
    k_agg<<<(Nn + NPB - 1) / NPB, 128>>>(b1);
    k_final<<<1, 256>>>(W2, b2, (float*)d_out);
}

// round 13
// speedup vs baseline: 3.1825x; 1.0598x over previous
#include <cuda_runtime.h>
#include <cuda_fp16.h>
#include <cstdint>

#define Nn   100000
#define Ee   1600000
#define Bb   2
#define FIN  116
#define EMBD 12
#define Hh   128
#define NS2  8           // K chunks of 16 (K padded to 128)
#define NC   128         // accumulator copies
#define NPB  64          // nodes per agg block (16 per warp)
#define NSB  98          // scan blocks (ceil(100000/1024))

#define QSCALE (127.0f / 8.0f)
#define QINV   (8.0f / 127.0f)

// -------- scratch (static device globals) --------
__device__ char  g_x8[(size_t)Nn * 256];   // [n][2h+b] int8 quantized xw1: 25.6 MB
__device__ int   g_cnt[Nn];
__device__ int   g_cursor[Nn];
__device__ float g_dis[Nn];
__device__ float g_tsum[Nn];
__device__ int   g_rowstart[Nn + 1];
__device__ int   g_bsum[NSB];
__device__ int   g_csrc[Ee];               // bits[0:17)=src, bits[17:32)=u15 dis[src]
__device__ float g_T[8 * Hh];
__device__ float g_acc[NC * 256];
__device__ uint32_t g_W1p[64][Hh];         // [kpair][h] fp16x2 packed (low half = even k)

// -------- host-side stream/event resources (created once at load; no device alloc) --------
static cudaStream_t g_s2;
static cudaEvent_t  g_e0, g_e1;
static struct SideStreamInit {
    SideStreamInit() {
        cudaStreamCreateWithFlags(&g_s2, cudaStreamNonBlocking);
        cudaEventCreateWithFlags(&g_e0, cudaEventDisableTiming);
        cudaEventCreateWithFlags(&g_e1, cudaEventDisableTiming);
    }
} g_ssi;

// -------- small helpers --------
__device__ __forceinline__ uint32_t packh(float lo, float hi) {
    __half2 h = __floats2half2_rn(lo, hi);
    return *(uint32_t*)&h;
}
__device__ __forceinline__ void cp16(uint32_t dst, const void* src, bool pred) {
    int sz = pred ? 16 : 0;
    asm volatile("cp.async.cg.shared.global [%0], [%1], 16, %2;\n" :: "r"(dst), "l"(src), "r"(sz));
}
#define CP_COMMIT() asm volatile("cp.async.commit_group;\n" ::: "memory")
#define CP_WAIT1()  asm volatile("cp.async.wait_group 1;\n" ::: "memory")

#define MMA_F16(Cr, Ar, B0, B1)                                               \
    asm volatile("mma.sync.aligned.m16n8k16.row.col.f32.f16.f16.f32 "         \
                 "{%0,%1,%2,%3},{%4,%5,%6,%7},{%8,%9},{%0,%1,%2,%3};"         \
                 : "+f"(Cr[0]), "+f"(Cr[1]), "+f"(Cr[2]), "+f"(Cr[3])         \
                 : "r"(Ar[0]), "r"(Ar[1]), "r"(Ar[2]), "r"(Ar[3]),            \
                   "r"(B0), "r"(B1))

__device__ __forceinline__ char quant8(float v) {
    int q = __float2int_rn(v * QSCALE);
    q = max(-127, min(127, q));
    return (char)q;
}
__device__ __forceinline__ __half2 u2h2(uint32_t u) {
    __half2_raw r; r.x = (unsigned short)(u & 0xffff); r.y = (unsigned short)(u >> 16);
    return r;
}

// -------- prep kernels --------
__global__ void k_zero() {
    int i = blockIdx.x * blockDim.x + threadIdx.x;
    int stride = gridDim.x * blockDim.x;
    for (int j = i; j < Nn; j += stride) { g_cnt[j] = 0; g_cursor[j] = 0; g_tsum[j] = 0.f; }
    for (int j = i; j < NC * 256; j += stride) g_acc[j] = 0.f;
}

__global__ void k_hist(const int* __restrict__ dst) {
    int i = blockIdx.x * blockDim.x + threadIdx.x;
    int stride = gridDim.x * blockDim.x;
    for (int e = i; e < Ee; e += stride) atomicAdd(&g_cnt[dst[e]], 1);
}

// ---- 3-phase parallel scan; phase A also computes dis = rsqrt(deg+1) ----
__global__ void k_scanA() {
    __shared__ int sd[1024];
    int t = threadIdx.x;
    int idx = blockIdx.x * 1024 + t;
    int v = (idx < Nn) ? g_cnt[idx] : 0;
    sd[t] = v;
    __syncthreads();
    for (int off = 1; off < 1024; off <<= 1) {
        int x = (t >= off) ? sd[t - off] : 0;
        __syncthreads();
        sd[t] += x;
        __syncthreads();
    }
    if (idx < Nn) {
        g_rowstart[idx] = sd[t] - v;   // block-local exclusive
        g_dis[idx] = rsqrtf((float)v + 1.0f);
    }
    if (t == 1023) g_bsum[blockIdx.x] = sd[1023];
}

__global__ void k_scanB() {
    int l = threadIdx.x;   // 32 threads
    int base = 4 * l;
    int v0 = (base + 0 < NSB) ? g_bsum[base + 0] : 0;
    int v1 = (base + 1 < NSB) ? g_bsum[base + 1] : 0;
    int v2 = (base + 2 < NSB) ? g_bsum[base + 2] : 0;
    int v3 = (base + 3 < NSB) ? g_bsum[base + 3] : 0;
    int t0 = v0, t1 = t0 + v1, t2 = t1 + v2, tot = t2 + v3;
    int incl = tot;
    #pragma unroll
    for (int off = 1; off < 32; off <<= 1) {
        int y = __shfl_up_sync(0xffffffffu, incl, off);
        if (l >= off) incl += y;
    }
    int excl = incl - tot;
    if (base + 0 < NSB) g_bsum[base + 0] = excl;
    if (base + 1 < NSB) g_bsum[base + 1] = excl + t0;
    if (base + 2 < NSB) g_bsum[base + 2] = excl + t1;
    if (base + 3 < NSB) g_bsum[base + 3] = excl + t2;
    if (l == 31) g_rowstart[Nn] = incl;
}

__global__ void k_scanC() {
    int t = threadIdx.x;
    int idx = blockIdx.x * 1024 + t;
    if (idx < Nn) g_rowstart[idx] += g_bsum[blockIdx.x];
}

// scatter CSR col (src + packed u15 dis[src]) + fused tsum accumulation
__global__ void k_scatter(const int* __restrict__ src, const int* __restrict__ dst) {
    int i = blockIdx.x * blockDim.x + threadIdx.x;
    int stride = gridDim.x * blockDim.x;
    for (int e = i; e < Ee; e += stride) {
        int d = dst[e], s = src[e];
        int pos = g_rowstart[d] + atomicAdd(&g_cursor[d], 1);
        float ds = g_dis[s];
        int q = (int)(ds * 32767.0f + 0.5f);
        g_csrc[pos] = s | (q << 17);
        atomicAdd(&g_tsum[s], g_dis[d]);
    }
}

// fused: W1 fp16 pack + embed table
__global__ void k_prep(const float* __restrict__ W1, const float* __restrict__ embed) {
    int idx = blockIdx.x * blockDim.x + threadIdx.x;
    if (idx < 64 * Hh) {
        int kp = idx >> 7, h = idx & 127;
        int k0 = 2 * kp, k1 = 2 * kp + 1;
        float w0 = (k0 < FIN) ? W1[k0 * Hh + h] : 0.f;
        float w1 = (k1 < FIN) ? W1[k1 * Hh + h] : 0.f;
        g_W1p[kp][h] = packh(w0, w1);
    } else if (idx < 64 * Hh + 8 * Hh) {
        int j2 = idx - 64 * Hh;
        int e = j2 >> 7, h = j2 & 127;
        float s = 0.f;
        #pragma unroll
        for (int j = 0; j < EMBD; j++) s += embed[e * EMBD + j] * W1[(FIN + j) * Hh + h];
        g_T[j2] = s;
    }
}

// -------- fp16 tensor-core GEMM (single pass), float4 cp.async staging, int8 store --------
__global__ __launch_bounds__(256, 2) void k_gemm(const float* __restrict__ node,
                                                 const int* __restrict__ ntype) {
    __shared__ float    As[2][128][20];     // [buf][row][k] (+4 pad)
    __shared__ uint32_t Bp[2][8][136];      // [buf][kpair][h]
    int b = blockIdx.y;
    int n0 = blockIdx.x * 128;
    int t = threadIdx.x;
    int w = t >> 5, lane = t & 31;
    int wm = w & 3, wn = w >> 2;         // warp tile: rows wm*32, cols wn*64
    int g = lane >> 2, t4 = lane & 3;
    const float* Abase = node + (size_t)b * Nn * FIN;

    uint32_t sAs = (uint32_t)__cvta_generic_to_shared(&As[0][0][0]);
    uint32_t sBp = (uint32_t)__cvta_generic_to_shared(&Bp[0][0][0]);

    float C[2][8][4];
    #pragma unroll
    for (int mt = 0; mt < 2; mt++)
        #pragma unroll
        for (int nt = 0; nt < 8; nt++)
            #pragma unroll
            for (int x = 0; x < 4; x++) C[mt][nt][x] = 0.f;

    auto issue = [&](int s) {
        int buf = s & 1;
        // A: 128 rows x 4 float4 = 512 f4, 2 per thread
        #pragma unroll
        for (int i = 0; i < 2; i++) {
            int lin = i * 256 + t;
            int row = lin >> 2, c = lin & 3;
            int n = n0 + row, k = s * 16 + 4 * c;
            bool ok = (n < Nn) && (k < FIN);
            const float* srcp = ok ? (Abase + (size_t)n * FIN + k) : Abase;
            cp16(sAs + (((buf * 128 + row) * 20 + 4 * c) << 2), srcp, ok);
        }
        // B: 8 kpairs x 32 f4 = 256 f4, 1 per thread
        {
            int c = t & 31, kp = (t >> 5) & 7;
            cp16(sBp + (((buf * 8 + kp) * 136 + 4 * c) << 2),
                 &g_W1p[s * 8 + kp][4 * c], true);
        }
    };

    issue(0);
    CP_COMMIT();

    for (int s = 0; s < NS2; s++) {
        if (s + 1 < NS2) issue(s + 1);
        CP_COMMIT();
        CP_WAIT1();
        __syncthreads();
        int buf = s & 1;

        uint32_t a[2][4];
        #pragma unroll
        for (int mt = 0; mt < 2; mt++) {
            int R = wm * 32 + mt * 16;
            float2 v0 = *(const float2*)&As[buf][R + g][2 * t4];
            float2 v1 = *(const float2*)&As[buf][R + g + 8][2 * t4];
            float2 v2 = *(const float2*)&As[buf][R + g][2 * t4 + 8];
            float2 v3 = *(const float2*)&As[buf][R + g + 8][2 * t4 + 8];
            a[mt][0] = packh(v0.x, v0.y);
            a[mt][1] = packh(v1.x, v1.y);
            a[mt][2] = packh(v2.x, v2.y);
            a[mt][3] = packh(v3.x, v3.y);
        }
        #pragma unroll
        for (int nt = 0; nt < 8; nt++) {
            int c = wn * 64 + nt * 8 + g;
            uint32_t b0 = Bp[buf][t4][c];
            uint32_t b1 = Bp[buf][t4 + 4][c];
            MMA_F16(C[0][nt], a[0], b0, b1);
            MMA_F16(C[1][nt], a[1], b0, b1);
        }
        __syncthreads();
    }

    // epilogue: add embed-table term, quantize to int8 at [n][2h+b]
    #pragma unroll
    for (int mt = 0; mt < 2; mt++) {
        int r0 = n0 + wm * 32 + mt * 16 + g;
        int r1 = r0 + 8;
        int e0 = (r0 < Nn) ? ntype[r0] : 0;
        int e1 = (r1 < Nn) ? ntype[r1] : 0;
        #pragma unroll
        for (int nt = 0; nt < 8; nt++) {
            int h = wn * 64 + nt * 8 + 2 * t4;
            if (r0 < Nn) {
                g_x8[(size_t)r0 * 256 + 2 * h + b]       = quant8(C[mt][nt][0] + g_T[e0 * Hh + h]);
                g_x8[(size_t)r0 * 256 + 2 * (h + 1) + b] = quant8(C[mt][nt][1] + g_T[e0 * Hh + h + 1]);
            }
            if (r1 < Nn) {
                g_x8[(size_t)r1 * 256 + 2 * h + b]       = quant8(C[mt][nt][2] + g_T[e1 * Hh + h]);
                g_x8[(size_t)r1 * 256 + 2 * (h + 1) + b] = quant8(C[mt][nt][3] + g_T[e1 * Hh + h + 1]);
            }
        }
    }
}

// -------- aggregation: warp-per-node, 1 LDG.64 per edge, half2 math --------
__device__ __forceinline__ void agg_edge(int2 v, __half2 W, __half2 HB, __half2 acc[4]) {
    uint32_t x0 = (uint32_t)v.x ^ 0x80808080u;
    uint32_t x1 = (uint32_t)v.y ^ 0x80808080u;
    acc[0] = __hfma2(__hsub2(u2h2(__byte_perm(x0, 0x64646464u, 0x5140)), HB), W, acc[0]);
    acc[1] = __hfma2(__hsub2(u2h2(__byte_perm(x0, 0x64646464u, 0x7362)), HB), W, acc[1]);
    acc[2] = __hfma2(__hsub2(u2h2(__byte_perm(x1, 0x64646464u, 0x5140)), HB), W, acc[2]);
    acc[3] = __hfma2(__hsub2(u2h2(__byte_perm(x1, 0x64646464u, 0x7362)), HB), W, acc[3]);
}

__global__ __launch_bounds__(128) void k_agg(const float* __restrict__ b1) {
    int w = threadIdx.x >> 5, l = threadIdx.x & 31;
    int ibase = blockIdx.x * NPB + w * 16;
    int ilim = ibase + 16; if (ilim > Nn) ilim = Nn;
    const float4 bb = ((const float4*)b1)[l];
    const __half2 HB = u2h2(0x64806480u);
    float2 facc[4] = {{0.f,0.f},{0.f,0.f},{0.f,0.f},{0.f,0.f}};

    for (int i = ibase; i < ilim; i++) {
        int beg = g_rowstart[i], end = g_rowstart[i + 1];
        __half2 acc[4];
        acc[0] = acc[1] = acc[2] = acc[3] = u2h2(0u);
        for (int c = beg; c < end; c += 32) {
            int m = end - c; if (m > 32) m = 32;
            int wd = (l < m) ? __ldg(&g_csrc[c + l]) : 0;
            int j = 0;
            for (; j + 4 <= m; j += 4) {
                int e0 = __shfl_sync(0xffffffffu, wd, j);
                int e1 = __shfl_sync(0xffffffffu, wd, j + 1);
                int e2 = __shfl_sync(0xffffffffu, wd, j + 2);
                int e3 = __shfl_sync(0xffffffffu, wd, j + 3);
                int2 v0 = __ldg((const int2*)(g_x8 + (size_t)(e0 & 0x1ffff) * 256) + l);
                int2 v1 = __ldg((const int2*)(g_x8 + (size_t)(e1 & 0x1ffff) * 256) + l);
                int2 v2 = __ldg((const int2*)(g_x8 + (size_t)(e2 & 0x1ffff) * 256) + l);
                int2 v3 = __ldg((const int2*)(g_x8 + (size_t)(e3 & 0x1ffff) * 256) + l);
                __half2 W0 = __float2half2_rn((float)((uint32_t)e0 >> 17) * (1.0f / 32767.0f));
                __half2 W1_ = __float2half2_rn((float)((uint32_t)e1 >> 17) * (1.0f / 32767.0f));
                __half2 W2_ = __float2half2_rn((float)((uint32_t)e2 >> 17) * (1.0f / 32767.0f));
                __half2 W3 = __float2half2_rn((float)((uint32_t)e3 >> 17) * (1.0f / 32767.0f));
                agg_edge(v0, W0, HB, acc);
                agg_edge(v1, W1_, HB, acc);
                agg_edge(v2, W2_, HB, acc);
                agg_edge(v3, W3, HB, acc);
            }
            for (; j < m; j++) {
                int e0 = __shfl_sync(0xffffffffu, wd, j);
                int2 v0 = __ldg((const int2*)(g_x8 + (size_t)(e0 & 0x1ffff) * 256) + l);
                __half2 W0 = __float2half2_rn((float)((uint32_t)e0 >> 17) * (1.0f / 32767.0f));
                agg_edge(v0, W0, HB, acc);
            }
        }
        // self term + epilogue
        int2 vs = __ldg((const int2*)(g_x8 + (size_t)i * 256) + l);
        __half2 sf[4];
        sf[0] = sf[1] = sf[2] = sf[3] = u2h2(0u);
        agg_edge(vs, __float2half2_rn(1.0f), HB, sf);
        float d = g_dis[i];
        float sI = d * (g_tsum[i] + d);
        float qd = QINV * d;
        const float* bbp = (const float*)&bb;
        #pragma unroll
        for (int k = 0; k < 4; k++) {
            float2 a2 = __half22float2(acc[k]);
            float2 s2 = __half22float2(sf[k]);
            float h0 = fmaxf(fmaf(qd, a2.x + d * s2.x, bbp[k]), 0.f);
            float h1 = fmaxf(fmaf(qd, a2.y + d * s2.y, bbp[k]), 0.f);
            facc[k].x += sI * h0;
            facc[k].y += sI * h1;
        }
    }
    int ci = ((blockIdx.x << 2) + w) & (NC - 1);
    float* dstp = g_acc + ci * 256;
    #pragma unroll
    for (int k = 0; k < 4; k++) {
        atomicAdd(dstp + 4 * l + k, facc[k].x);
        atomicAdd(dstp + 128 + 4 * l + k, facc[k].y);
    }
}

// -------- final: out[b][h2] = b2 + (1/N) * v[b] @ W2 --------
__global__ void k_final(const float* __restrict__ W2, const float* __restrict__ b2,
                        float* __restrict__ out) {
    __shared__ float v[256];
    int t = threadIdx.x;
    float s = 0.f;
    for (int c = 0; c < NC; c++) s += g_acc[c * 256 + t];
    v[t] = s * (1.0f / (float)Nn);
    __syncthreads();
    int b = t >> 7, h2 = t & 127;
    float o = b2[h2];
    for (int f = 0; f < 128; f++) o += v[b * 128 + f] * W2[f * Hh + h2];
    out[b * Hh + h2] = o;
}

extern "C" void kernel_launch(void* const* d_in, const int* in_sizes, int n_in,
                              void* d_out, int out_size) {
    const float* node  = (const float*)d_in[0];
    const int*   ntype = (const int*)d_in[1];
    const int*   ei    = (const int*)d_in[2];
    const float* embed = (const float*)d_in[3];
    const float* W1    = (const float*)d_in[4];
    const float* b1    = (const float*)d_in[5];
    const float* W2    = (const float*)d_in[6];
    const float* b2    = (const float*)d_in[7];
    const int* src = ei;
    const int* dst = ei + Ee;

    // fork: side branch runs W1 prep + GEMM concurrently with the CSR build chain
    cudaEventRecord(g_e0, 0);
    cudaStreamWaitEvent(g_s2, g_e0, 0);

    // side branch (independent of edges)
    k_prep<<<(64 * Hh + 8 * Hh + 255) / 256, 256, 0, g_s2>>>(W1, embed);
    k_gemm<<<dim3((Nn + 127) / 128, Bb), 256, 0, g_s2>>>(node, ntype);
    cudaEventRecord(g_e1, g_s2);

    // main branch: CSR build
    k_zero<<<256, 256>>>();
    k_hist<<<1024, 256>>>(dst);
    k_scanA<<<NSB, 1024>>>();
    k_scanB<<<1, 32>>>();
    k_scanC<<<NSB, 1024>>>();
    k_scatter<<<1024, 256>>>(src, dst);

    // join, then aggregate + finalize
    cudaStreamWaitEvent(0, g_e1, 0);
    k_agg<<<(Nn + NPB - 1) / NPB, 128>>>(b1);
    k_final<<<1, 256>>>(W2, b2, (float*)d_out);
}